// round 4
// baseline (speedup 1.0000x reference)
#include <cuda_runtime.h>
#include <math.h>
#include <stdint.h>

#define S     4096
#define MDIM  2048
#define E     32
#define TOPK  2
#define CAP   256

static const size_t SEC = (size_t)S * E * CAP;   // 33,554,432

// ---------------- scratch (device globals; no allocation allowed) ----------
__device__ float g_logits[S * E];
__device__ float g_gates[S * E];
__device__ int   g_top_idx[S * TOPK];
__device__ float g_top_gate[S * TOPK];
__device__ int   g_ecnt[E];                  // pre-capacity expert counts
__device__ float g_elist_val[E * S];         // per-expert selected logit values
__device__ int   g_elist_tok[E * S];         // packed: (token<<1)|kslot
__device__ int   g_slot[S * TOPK];           // -1 if dropped, else slot in expert
__device__ float g_gsum[E];                  // deterministic column sums of gates

// ---------------- init ----------------
__global__ void init_k() {
    int i = blockIdx.x * blockDim.x + threadIdx.x;
    if (i < E) g_ecnt[i] = 0;
    if (i < S * TOPK) g_slot[i] = -1;
}

// ---------------- logits GEMM: [S,M] x [E,M]^T -> [S,E] -------------------
#define BT 32
#define KC 128
__global__ __launch_bounds__(256) void gemm_k(const float* __restrict__ x,
                                              const float* __restrict__ wg) {
    __shared__ float xs[BT][KC + 4];   // stride 132 floats (16B aligned rows)
    __shared__ float ws[E][KC + 1];    // stride 129 -> conflict-free lane reads

    const int t0   = blockIdx.x * BT;
    const int tid  = threadIdx.x;
    const int lane = tid & 31;         // expert id
    const int wrp  = tid >> 5;         // 8 warps, 4 tokens each
    const int tb   = wrp * 4;

    float acc0 = 0.f, acc1 = 0.f, acc2 = 0.f, acc3 = 0.f;

    for (int kc = 0; kc < MDIM; kc += KC) {
        // load x tile: BT*KC floats via float4
        for (int i = tid; i < BT * (KC / 4); i += 256) {
            int row = i / (KC / 4), c4 = i % (KC / 4);
            float4 v = *(const float4*)&x[(size_t)(t0 + row) * MDIM + kc + c4 * 4];
            *(float4*)&xs[row][c4 * 4] = v;
        }
        // load w tile: E*KC floats
        for (int i = tid; i < E * (KC / 4); i += 256) {
            int row = i / (KC / 4), c4 = i % (KC / 4);
            float4 v = *(const float4*)&wg[(size_t)row * MDIM + kc + c4 * 4];
            ws[row][c4 * 4 + 0] = v.x; ws[row][c4 * 4 + 1] = v.y;
            ws[row][c4 * 4 + 2] = v.z; ws[row][c4 * 4 + 3] = v.w;
        }
        __syncthreads();

        #pragma unroll
        for (int k = 0; k < KC; k += 4) {
            float w0 = ws[lane][k + 0], w1 = ws[lane][k + 1];
            float w2 = ws[lane][k + 2], w3 = ws[lane][k + 3];
            float4 a;
            a = *(const float4*)&xs[tb + 0][k];
            acc0 += a.x * w0 + a.y * w1 + a.z * w2 + a.w * w3;
            a = *(const float4*)&xs[tb + 1][k];
            acc1 += a.x * w0 + a.y * w1 + a.z * w2 + a.w * w3;
            a = *(const float4*)&xs[tb + 2][k];
            acc2 += a.x * w0 + a.y * w1 + a.z * w2 + a.w * w3;
            a = *(const float4*)&xs[tb + 3][k];
            acc3 += a.x * w0 + a.y * w1 + a.z * w2 + a.w * w3;
        }
        __syncthreads();
    }
    g_logits[(size_t)(t0 + tb + 0) * E + lane] = acc0;
    g_logits[(size_t)(t0 + tb + 1) * E + lane] = acc1;
    g_logits[(size_t)(t0 + tb + 2) * E + lane] = acc2;
    g_logits[(size_t)(t0 + tb + 3) * E + lane] = acc3;
}

// ---------------- gate: softmax + top-2 + expert-list append ---------------
__global__ __launch_bounds__(256) void gate_k() {
    const int s    = blockIdx.x * 8 + (threadIdx.x >> 5);
    const int lane = threadIdx.x & 31;
    const float v  = g_logits[s * E + lane];

    // top-1 with lowest-index tie-break
    float bv = v; int bi = lane;
    #pragma unroll
    for (int off = 16; off; off >>= 1) {
        float ov = __shfl_xor_sync(0xFFFFFFFFu, bv, off);
        int   oi = __shfl_xor_sync(0xFFFFFFFFu, bi, off);
        if (ov > bv || (ov == bv && oi < bi)) { bv = ov; bi = oi; }
    }
    // top-2: exclude bi
    float v2 = (lane == bi) ? -INFINITY : v;
    float cv = v2; int ci = lane;
    #pragma unroll
    for (int off = 16; off; off >>= 1) {
        float ov = __shfl_xor_sync(0xFFFFFFFFu, cv, off);
        int   oi = __shfl_xor_sync(0xFFFFFFFFu, ci, off);
        if (ov > cv || (ov == cv && oi < bi && oi < ci)) { cv = ov; ci = oi; }
    }
    // (standard tie-break: take the better (value, lower-index) pair)
    // redo cleanly to be safe:
    cv = v2; ci = lane;
    #pragma unroll
    for (int off = 16; off; off >>= 1) {
        float ov = __shfl_xor_sync(0xFFFFFFFFu, cv, off);
        int   oi = __shfl_xor_sync(0xFFFFFFFFu, ci, off);
        if (ov > cv || (ov == cv && oi < ci)) { cv = ov; ci = oi; }
    }

    // softmax over full row (max-subtracted, matches jax)
    float ex  = expf(v - bv);
    float sum = ex;
    #pragma unroll
    for (int off = 16; off; off >>= 1) sum += __shfl_xor_sync(0xFFFFFFFFu, sum, off);
    float gate = ex / sum;
    g_gates[s * E + lane] = gate;

    float g1 = __shfl_sync(0xFFFFFFFFu, gate, bi);
    float g2 = __shfl_sync(0xFFFFFFFFu, gate, ci);

    if (lane == 0) {
        g_top_idx[2 * s + 0] = bi;  g_top_idx[2 * s + 1] = ci;
        g_top_gate[2 * s + 0] = g1; g_top_gate[2 * s + 1] = g2;
        int p0 = atomicAdd(&g_ecnt[bi], 1);
        g_elist_val[bi * S + p0] = bv;
        g_elist_tok[bi * S + p0] = (s << 1);
        int p1 = atomicAdd(&g_ecnt[ci], 1);
        g_elist_val[ci * S + p1] = cv;
        g_elist_tok[ci * S + p1] = (s << 1) | 1;
    }
}

// ---------------- deterministic per-expert gate column sums ---------------
__global__ void gsum_k() {
    const int e = blockIdx.x, tid = threadIdx.x;
    __shared__ float sm[256];
    float a = 0.f;
    for (int t = tid; t < S; t += 256) a += g_gates[t * E + e];
    sm[tid] = a; __syncthreads();
    for (int o = 128; o; o >>= 1) { if (tid < o) sm[tid] += sm[tid + o]; __syncthreads(); }
    if (tid == 0) g_gsum[e] = sm[0];
}

// ---------------- capacity drop (probs policy) + slot assignment ----------
__global__ __launch_bounds__(512) void cap_k() {
    const int e = blockIdx.x;
    const int n = g_ecnt[e];
    __shared__ float sv[S];
    __shared__ int   st[S];
    __shared__ unsigned char sf[S];

    for (int i = threadIdx.x; i < n; i += blockDim.x) {
        sv[i] = g_elist_val[e * S + i];
        st[i] = g_elist_tok[e * S + i];
    }
    __syncthreads();

    // survive iff value > 0 (zeros of 3840+ unselected tokens outrank any
    // negative) AND rank-by-(value desc, token asc) < CAP
    for (int i = threadIdx.x; i < n; i += blockDim.x) {
        float vi = sv[i]; int ti = st[i] >> 1;
        int surv = 0;
        if (vi > 0.f) {
            int rank = 0;
            for (int j = 0; j < n; j++) {
                float vj = sv[j];
                rank += (vj > vi) || (vj == vi && (st[j] >> 1) < ti);
            }
            surv = (rank < CAP);
        }
        sf[i] = (unsigned char)surv;
    }
    __syncthreads();

    // slot = token-order cumsum among survivors (cumsum(mask)-1)
    for (int i = threadIdx.x; i < n; i += blockDim.x) {
        if (sf[i]) {
            int ti = st[i] >> 1, slot = 0;
            for (int j = 0; j < n; j++) slot += (sf[j] && (st[j] >> 1) < ti);
            g_slot[st[i]] = slot;
        }
    }
}

// ---------------- finalize: l_aux, sparse combine/dispatch, exp_counts ----
__global__ void final_k(float* __restrict__ out) {
    const int s = blockIdx.x * blockDim.x + threadIdx.x;
    if (s < S) {
        int   sl0 = g_slot[2 * s + 0], sl1 = g_slot[2 * s + 1];
        float g0  = g_top_gate[2 * s + 0], g1 = g_top_gate[2 * s + 1];
        float denom = 0.f; int L = 0;
        if (sl0 >= 0) { denom += g0; L += sl0; }
        if (sl1 >= 0) { denom += g1; L += sl1; }
        denom = fmaxf(denom, 1.1920929e-7f);
        if (L < CAP) {
            float* comb = out + 1;
            float* disp = out + 1 + SEC;
            if (sl0 >= 0) {
                size_t off = ((size_t)s * E + g_top_idx[2 * s + 0]) * CAP + L;
                comb[off] = g0 / denom; disp[off] = 1.f;
            }
            if (sl1 >= 0) {
                size_t off = ((size_t)s * E + g_top_idx[2 * s + 1]) * CAP + L;
                comb[off] = g1 / denom; disp[off] = 1.f;
            }
        }
    }
    if (blockIdx.x == 0 && threadIdx.x == 0) {
        float acc = 0.f;
        for (int e = 0; e < E; e++) acc += g_gsum[e] * (float)g_ecnt[e];
        // l_aux = (E/K) * sum(gsum*cnt) / S^2
        out[0] = acc * ((float)E / (float)TOPK) / ((float)S * (float)S);
    }
    if (blockIdx.x == 0 && threadIdx.x < E)
        out[1 + 2 * SEC + threadIdx.x] = (float)g_ecnt[threadIdx.x];
}

// ---------------- launch ---------------------------------------------------
extern "C" void kernel_launch(void* const* d_in, const int* in_sizes, int n_in,
                              void* d_out, int out_size) {
    const float* x;
    const float* wg;
    if (in_sizes[0] == S * MDIM) { x = (const float*)d_in[0]; wg = (const float*)d_in[1]; }
    else                         { x = (const float*)d_in[1]; wg = (const float*)d_in[0]; }
    float* out = (float*)d_out;

    cudaMemsetAsync(d_out, 0, (size_t)out_size * sizeof(float));
    init_k<<<(S * TOPK + 255) / 256, 256>>>();
    gemm_k<<<S / BT, 256>>>(x, wg);
    gate_k<<<S / 8, 256>>>();
    gsum_k<<<E, 256>>>();
    cap_k<<<E, 512>>>();
    final_k<<<(S + 255) / 256, 256>>>(out);
}

// round 5
// speedup vs baseline: 1.0498x; 1.0498x over previous
#include <cuda_runtime.h>
#include <math.h>
#include <stdint.h>

#define S     4096
#define MDIM  2048
#define E     32
#define TOPK  2
#define CAP   256

#define BT    32            // tokens per GEMM block
#define KC    128           // k-chunk
#define GEMM_BLOCKS (S / BT)     // 128
#define ZERO_BLOCKS 1024

static const size_t SEC = (size_t)S * E * CAP;   // 33,554,432

// ---------------- scratch (device globals; no allocation allowed) ----------
__device__ int   g_top_idx[S * TOPK];
__device__ float g_top_gate[S * TOPK];
__device__ int   g_ecnt[E];                    // pre-capacity expert counts
__device__ float g_elist_val[E * S];           // per-expert selected raw logits
__device__ int   g_elist_tok[E * S];           // packed: (token<<1)|kslot
__device__ int   g_slot[S * TOPK];             // -1 if dropped, else slot
__device__ float g_part[GEMM_BLOCKS * E];      // per-block gate column partials

// ---------------- init: zero expert counters only --------------------------
__global__ void init_k() { if (threadIdx.x < E) g_ecnt[threadIdx.x] = 0; }

// ---------------- fused: zero(d_out) || GEMM + gating + partial sums -------
__global__ __launch_bounds__(256) void fused_k(const float* __restrict__ x,
                                               const float* __restrict__ wg,
                                               float* __restrict__ out,
                                               int out_elems) {
    __shared__ float xs[BT][KC + 4];   // 16.9 KB
    __shared__ float ws[E][KC + 1];    // 16.5 KB
    __shared__ float sred[8][E];       // gate partial reduction

    // ---------- zero path: blocks [GEMM_BLOCKS, GEMM_BLOCKS+ZERO_BLOCKS) ---
    if (blockIdx.x >= GEMM_BLOCKS) {
        const size_t nvec   = (size_t)out_elems >> 2;
        const size_t stride = (size_t)ZERO_BLOCKS * 256;
        size_t i = (size_t)(blockIdx.x - GEMM_BLOCKS) * 256 + threadIdx.x;
        float4* o4 = (float4*)out;
        const float4 z = make_float4(0.f, 0.f, 0.f, 0.f);
        for (; i < nvec; i += stride) o4[i] = z;
        if (blockIdx.x == GEMM_BLOCKS && threadIdx.x < ((unsigned)out_elems & 3u))
            out[(nvec << 2) + threadIdx.x] = 0.f;
        return;
    }

    // ---------- GEMM path: 32 tokens x 32 experts --------------------------
    const int t0   = blockIdx.x * BT;
    const int tid  = threadIdx.x;
    const int lane = tid & 31;         // expert id
    const int wrp  = tid >> 5;         // 8 warps, 4 tokens each
    const int tb   = wrp * 4;

    float acc0 = 0.f, acc1 = 0.f, acc2 = 0.f, acc3 = 0.f;

    for (int kc = 0; kc < MDIM; kc += KC) {
        for (int i = tid; i < BT * (KC / 4); i += 256) {
            int row = i / (KC / 4), c4 = i % (KC / 4);
            float4 v = *(const float4*)&x[(size_t)(t0 + row) * MDIM + kc + c4 * 4];
            *(float4*)&xs[row][c4 * 4] = v;
        }
        for (int i = tid; i < E * (KC / 4); i += 256) {
            int row = i / (KC / 4), c4 = i % (KC / 4);
            float4 v = *(const float4*)&wg[(size_t)row * MDIM + kc + c4 * 4];
            ws[row][c4 * 4 + 0] = v.x; ws[row][c4 * 4 + 1] = v.y;
            ws[row][c4 * 4 + 2] = v.z; ws[row][c4 * 4 + 3] = v.w;
        }
        __syncthreads();

        #pragma unroll
        for (int k = 0; k < KC; k += 4) {
            float w0 = ws[lane][k + 0], w1 = ws[lane][k + 1];
            float w2 = ws[lane][k + 2], w3 = ws[lane][k + 3];
            float4 a;
            a = *(const float4*)&xs[tb + 0][k];
            acc0 += a.x * w0 + a.y * w1 + a.z * w2 + a.w * w3;
            a = *(const float4*)&xs[tb + 1][k];
            acc1 += a.x * w0 + a.y * w1 + a.z * w2 + a.w * w3;
            a = *(const float4*)&xs[tb + 2][k];
            acc2 += a.x * w0 + a.y * w1 + a.z * w2 + a.w * w3;
            a = *(const float4*)&xs[tb + 3][k];
            acc3 += a.x * w0 + a.y * w1 + a.z * w2 + a.w * w3;
        }
        __syncthreads();
    }

    // ---------- gating epilogue: warp owns full rows for 4 tokens ----------
    float accs[4] = {acc0, acc1, acc2, acc3};
    float pacc = 0.f;   // this lane's expert-column gate partial

    #pragma unroll
    for (int i = 0; i < 4; i++) {
        const int s   = t0 + tb + i;
        const float v = accs[i];

        // top-1 (lowest-index tie-break, matches jax.lax.top_k)
        float bv = v; int bi = lane;
        #pragma unroll
        for (int off = 16; off; off >>= 1) {
            float ov = __shfl_xor_sync(0xFFFFFFFFu, bv, off);
            int   oi = __shfl_xor_sync(0xFFFFFFFFu, bi, off);
            if (ov > bv || (ov == bv && oi < bi)) { bv = ov; bi = oi; }
        }
        // top-2: exclude bi
        float v2 = (lane == bi) ? -INFINITY : v;
        float cv = v2; int ci = lane;
        #pragma unroll
        for (int off = 16; off; off >>= 1) {
            float ov = __shfl_xor_sync(0xFFFFFFFFu, cv, off);
            int   oi = __shfl_xor_sync(0xFFFFFFFFu, ci, off);
            if (ov > cv || (ov == cv && oi < ci)) { cv = ov; ci = oi; }
        }

        // softmax (max-subtracted)
        float ex  = expf(v - bv);
        float sum = ex;
        #pragma unroll
        for (int off = 16; off; off >>= 1) sum += __shfl_xor_sync(0xFFFFFFFFu, sum, off);
        float gate = ex / sum;
        pacc += gate;

        float g1 = __shfl_sync(0xFFFFFFFFu, gate, bi);
        float g2 = __shfl_sync(0xFFFFFFFFu, gate, ci);

        if (lane == 0) {
            g_top_idx[2 * s + 0] = bi;  g_top_idx[2 * s + 1] = ci;
            g_top_gate[2 * s + 0] = g1; g_top_gate[2 * s + 1] = g2;
            int p0 = atomicAdd(&g_ecnt[bi], 1);
            g_elist_val[bi * S + p0] = bv;
            g_elist_tok[bi * S + p0] = (s << 1);
            int p1 = atomicAdd(&g_ecnt[ci], 1);
            g_elist_val[ci * S + p1] = cv;
            g_elist_tok[ci * S + p1] = (s << 1) | 1;
        }
    }

    // per-block deterministic gate column partials (fixed reduction order)
    sred[wrp][lane] = pacc;
    __syncthreads();
    if (wrp == 0) {
        float a = 0.f;
        #pragma unroll
        for (int w = 0; w < 8; w++) a += sred[w][lane];
        g_part[blockIdx.x * E + lane] = a;
    }
}

// ---------------- capacity drop (probs policy) + slot assignment ----------
__global__ __launch_bounds__(512) void cap_k() {
    const int e = blockIdx.x;
    const int n = g_ecnt[e];
    __shared__ float sv[S];
    __shared__ int   st[S];
    __shared__ unsigned char sf[S];

    for (int i = threadIdx.x; i < n; i += blockDim.x) {
        sv[i] = g_elist_val[e * S + i];
        st[i] = g_elist_tok[e * S + i];
    }
    __syncthreads();

    // survive iff logit > 0 (the >=3840 zero columns outrank any negative)
    // AND rank-by-(value desc, token asc) < CAP
    for (int i = threadIdx.x; i < n; i += blockDim.x) {
        float vi = sv[i]; int ti = st[i] >> 1;
        int surv = 0;
        if (vi > 0.f) {
            int rank = 0;
            for (int j = 0; j < n; j++) {
                float vj = sv[j];
                rank += (vj > vi) || (vj == vi && (st[j] >> 1) < ti);
            }
            surv = (rank < CAP);
        }
        sf[i] = (unsigned char)surv;
    }
    __syncthreads();

    // slot = token-order cumsum among survivors; non-survivors get -1
    for (int i = threadIdx.x; i < n; i += blockDim.x) {
        if (sf[i]) {
            int ti = st[i] >> 1, slot = 0;
            for (int j = 0; j < n; j++) slot += (sf[j] && (st[j] >> 1) < ti);
            g_slot[st[i]] = slot;
        } else {
            g_slot[st[i]] = -1;
        }
    }
}

// ---------------- finalize: l_aux, sparse scatter, exp_counts -------------
__global__ __launch_bounds__(256) void final_k(float* __restrict__ out) {
    __shared__ float cs[E];
    const int s = blockIdx.x * blockDim.x + threadIdx.x;
    if (s < S) {
        int   sl0 = g_slot[2 * s + 0], sl1 = g_slot[2 * s + 1];
        float g0  = g_top_gate[2 * s + 0], g1 = g_top_gate[2 * s + 1];
        float denom = 0.f; int L = 0;
        if (sl0 >= 0) { denom += g0; L += sl0; }
        if (sl1 >= 0) { denom += g1; L += sl1; }
        denom = fmaxf(denom, 1.1920929e-7f);
        if (L < CAP) {
            float* comb = out + 1;
            float* disp = out + 1 + SEC;
            if (sl0 >= 0) {
                size_t off = ((size_t)s * E + g_top_idx[2 * s + 0]) * CAP + L;
                comb[off] = g0 / denom; disp[off] = 1.f;
            }
            if (sl1 >= 0) {
                size_t off = ((size_t)s * E + g_top_idx[2 * s + 1]) * CAP + L;
                comb[off] = g1 / denom; disp[off] = 1.f;
            }
        }
    }
    if (blockIdx.x == 0) {
        if (threadIdx.x < E) {
            float a = 0.f;
            for (int b = 0; b < GEMM_BLOCKS; b++) a += g_part[b * E + threadIdx.x];
            cs[threadIdx.x] = a * (float)g_ecnt[threadIdx.x];
            out[1 + 2 * SEC + threadIdx.x] = (float)g_ecnt[threadIdx.x];
        }
        __syncthreads();
        if (threadIdx.x == 0) {
            float acc = 0.f;
            #pragma unroll
            for (int e = 0; e < E; e++) acc += cs[e];
            // l_aux = (E/K) * sum(colsum * cnt) / S^2
            out[0] = acc * ((float)E / (float)TOPK) / ((float)S * (float)S);
        }
    }
}

// ---------------- launch ---------------------------------------------------
extern "C" void kernel_launch(void* const* d_in, const int* in_sizes, int n_in,
                              void* d_out, int out_size) {
    const float* x;
    const float* wg;
    if (in_sizes[0] == S * MDIM) { x = (const float*)d_in[0]; wg = (const float*)d_in[1]; }
    else                         { x = (const float*)d_in[1]; wg = (const float*)d_in[0]; }
    float* out = (float*)d_out;

    init_k<<<1, 32>>>();
    fused_k<<<GEMM_BLOCKS + ZERO_BLOCKS, 256>>>(x, wg, out, out_size);
    cap_k<<<E, 512>>>();
    final_k<<<(S + 255) / 256, 256>>>(out);
}